// round 1
// baseline (speedup 1.0000x reference)
#include <cuda_runtime.h>
#include <math.h>

// Problem constants
#define BB 4
#define SS 2048
#define DD 1024
#define HH 16
#define HD 64
#define NT (BB * SS)        // 8192 tokens
#define D3 (3 * DD)         // 3072

// Scratch (device globals — no runtime allocation)
static __device__ float g_qkv[(size_t)NT * D3];    // [8192, 3072]
static __device__ float g_attn[(size_t)NT * DD];   // [8192, 1024]

// ---------------------------------------------------------------------------
// SGEMM: C[M,N] = A[M,K] @ B[K,N] + bias[N]
// 128x128 block tile, BK=16, 8x8 per thread, 256 threads. M,N %128==0, K%16==0.
// ---------------------------------------------------------------------------
__global__ __launch_bounds__(256) void sgemm_bias(
    const float* __restrict__ A, const float* __restrict__ B,
    const float* __restrict__ bias, float* __restrict__ C,
    int M, int N, int K)
{
    __shared__ float As[16][128];   // transposed A tile: As[k][m]
    __shared__ float Bs[16][128];   // Bs[k][n]

    const int tid = threadIdx.x;
    const int bm = blockIdx.y, bn = blockIdx.x;

    const int a_row = tid >> 2;        // 0..63
    const int a_col = tid & 3;         // 0..3 (float4 index along K)
    const int b_row = tid >> 5;        // 0..7
    const int b_col = tid & 31;        // 0..31 (float4 index along N)

    const int ty = tid >> 4;           // 0..15
    const int tx = tid & 15;           // 0..15

    const float* Ab = A + (size_t)(bm * 128) * K;
    const float* Bb = B + bn * 128;

    float acc[8][8];
#pragma unroll
    for (int i = 0; i < 8; i++)
#pragma unroll
        for (int j = 0; j < 8; j++) acc[i][j] = 0.0f;

    for (int k0 = 0; k0 < K; k0 += 16) {
#pragma unroll
        for (int r = 0; r < 2; r++) {
            float4 v = *(const float4*)(Ab + (size_t)(a_row + 64 * r) * K + k0 + a_col * 4);
            As[a_col * 4 + 0][a_row + 64 * r] = v.x;
            As[a_col * 4 + 1][a_row + 64 * r] = v.y;
            As[a_col * 4 + 2][a_row + 64 * r] = v.z;
            As[a_col * 4 + 3][a_row + 64 * r] = v.w;
        }
#pragma unroll
        for (int r = 0; r < 2; r++) {
            *(float4*)(&Bs[b_row + 8 * r][b_col * 4]) =
                *(const float4*)(Bb + (size_t)(k0 + b_row + 8 * r) * N + b_col * 4);
        }
        __syncthreads();

#pragma unroll
        for (int k = 0; k < 16; k++) {
            float ra[8], rb[8];
            *(float4*)(ra)     = *(const float4*)(&As[k][ty * 8]);
            *(float4*)(ra + 4) = *(const float4*)(&As[k][ty * 8 + 4]);
            *(float4*)(rb)     = *(const float4*)(&Bs[k][tx * 8]);
            *(float4*)(rb + 4) = *(const float4*)(&Bs[k][tx * 8 + 4]);
#pragma unroll
            for (int i = 0; i < 8; i++)
#pragma unroll
                for (int j = 0; j < 8; j++)
                    acc[i][j] += ra[i] * rb[j];
        }
        __syncthreads();
    }

#pragma unroll
    for (int i = 0; i < 8; i++) {
        const int row = bm * 128 + ty * 8 + i;
#pragma unroll
        for (int j = 0; j < 8; j += 4) {
            const int col = bn * 128 + tx * 8 + j;
            float4 o;
            o.x = acc[i][j + 0] + bias[col + 0];
            o.y = acc[i][j + 1] + bias[col + 1];
            o.z = acc[i][j + 2] + bias[col + 2];
            o.w = acc[i][j + 3] + bias[col + 3];
            *(float4*)(C + (size_t)row * N + col) = o;
        }
    }
}

// ---------------------------------------------------------------------------
// Flash attention (causal). One thread = one query row. Block = 128 q rows of
// one (batch, head). K/V streamed in 32-key smem tiles, read via broadcast.
// qkv layout: [token, 3072] with q|k|v at col offsets 0|1024|2048, head h at +h*64.
// ---------------------------------------------------------------------------
__global__ __launch_bounds__(128) void flash_attn(
    const float* __restrict__ qkv, float* __restrict__ attn_out)
{
    __shared__ float4 ks4[32][16];   // 32 keys x 64 dims
    __shared__ float4 vs4[32][16];

    const int tid   = threadIdx.x;
    const int qtile = blockIdx.x;        // 0..15
    const int bh    = blockIdx.y;        // 0..63
    const int b     = bh >> 4;
    const int h     = bh & 15;

    const int bS = b * SS;
    const int qi = qtile * 128 + tid;    // query index within sequence

    // Load q row into registers, pre-scaled by 1/sqrt(64)
    float4 q4[16];
    {
        const float* qp = qkv + (size_t)(bS + qi) * D3 + h * HD;
#pragma unroll
        for (int c = 0; c < 16; c++) {
            float4 v = *(const float4*)(qp + c * 4);
            v.x *= 0.125f; v.y *= 0.125f; v.z *= 0.125f; v.w *= 0.125f;
            q4[c] = v;
        }
    }

    float4 acc4[16];
#pragma unroll
    for (int c = 0; c < 16; c++) acc4[c] = make_float4(0.f, 0.f, 0.f, 0.f);
    float m = -1e30f, l = 0.0f;

    const int n_tiles = (qtile + 1) * 4;   // causal: keys only up to this q tile
    for (int kt = 0; kt < n_tiles; kt++) {
        const int k0 = kt * 32;
        __syncthreads();
#pragma unroll
        for (int r = 0; r < 4; r++) {
            const int i = tid + 128 * r;
            const int row = i >> 4, col = i & 15;
            const size_t base = (size_t)(bS + k0 + row) * D3 + h * HD + col * 4;
            ks4[row][col] = *(const float4*)(qkv + base + DD);
            vs4[row][col] = *(const float4*)(qkv + base + 2 * DD);
        }
        __syncthreads();

        float s[32];
#pragma unroll
        for (int j = 0; j < 32; j++) {
            float sum = 0.0f;
#pragma unroll
            for (int c = 0; c < 16; c++) {
                float4 kk = ks4[j][c];
                sum += q4[c].x * kk.x + q4[c].y * kk.y + q4[c].z * kk.z + q4[c].w * kk.w;
            }
            s[j] = sum;
        }

        if (k0 + 31 > qi) {
#pragma unroll
            for (int j = 0; j < 32; j++)
                if (k0 + j > qi) s[j] = -1e30f;
        }

        float m_new = m;
#pragma unroll
        for (int j = 0; j < 32; j++) m_new = fmaxf(m_new, s[j]);

        const float alpha = __expf(m - m_new);
        l *= alpha;
#pragma unroll
        for (int c = 0; c < 16; c++) {
            acc4[c].x *= alpha; acc4[c].y *= alpha;
            acc4[c].z *= alpha; acc4[c].w *= alpha;
        }

#pragma unroll
        for (int j = 0; j < 32; j++) {
            const float p = __expf(s[j] - m_new);
            l += p;
            s[j] = p;
        }

#pragma unroll
        for (int j = 0; j < 32; j++) {
            const float p = s[j];
#pragma unroll
            for (int c = 0; c < 16; c++) {
                float4 vv = vs4[j][c];
                acc4[c].x += p * vv.x; acc4[c].y += p * vv.y;
                acc4[c].z += p * vv.z; acc4[c].w += p * vv.w;
            }
        }
        m = m_new;
    }

    const float inv_l = 1.0f / l;
    float* op = attn_out + (size_t)(bS + qi) * DD + h * HD;
#pragma unroll
    for (int c = 0; c < 16; c++) {
        float4 o = acc4[c];
        o.x *= inv_l; o.y *= inv_l; o.z *= inv_l; o.w *= inv_l;
        *(float4*)(op + c * 4) = o;
    }
}

// ---------------------------------------------------------------------------
extern "C" void kernel_launch(void* const* d_in, const int* in_sizes, int n_in,
                              void* d_out, int out_size)
{
    const float* hidden   = (const float*)d_in[0];  // [B,S,D]
    const float* c_attn_w = (const float*)d_in[1];  // [D,3D]
    const float* c_attn_b = (const float*)d_in[2];  // [3D]
    const float* c_proj_w = (const float*)d_in[3];  // [D,D]
    const float* c_proj_b = (const float*)d_in[4];  // [D]
    float* out = (float*)d_out;                     // [B,S,D]

    float* qkv  = nullptr;
    float* attn = nullptr;
    cudaGetSymbolAddress((void**)&qkv,  g_qkv);
    cudaGetSymbolAddress((void**)&attn, g_attn);

    // 1) QKV projection: [8192,1024] @ [1024,3072] + b
    {
        dim3 grid(D3 / 128, NT / 128);
        sgemm_bias<<<grid, 256>>>(hidden, c_attn_w, c_attn_b, qkv, NT, D3, DD);
    }
    // 2) Causal flash attention per (b,h), 128-query tiles
    {
        dim3 grid(SS / 128, BB * HH);
        flash_attn<<<grid, 128>>>(qkv, attn);
    }
    // 3) Output projection: [8192,1024] @ [1024,1024] + b
    {
        dim3 grid(DD / 128, NT / 128);
        sgemm_bias<<<grid, 256>>>(attn, c_proj_w, c_proj_b, out, NT, DD, DD);
    }
}

// round 3
// speedup vs baseline: 1.2385x; 1.2385x over previous
#include <cuda_runtime.h>
#include <cuda_bf16.h>
#include <cstdint>

// Problem constants
#define BB 4
#define SS 2048
#define DD 1024
#define HH 16
#define HD 64
#define NT (BB * SS)        // 8192 tokens
#define D3 (3 * DD)         // 3072

// ---------------------------------------------------------------------------
// Scratch (device globals — no runtime allocation)
// ---------------------------------------------------------------------------
static __device__ float          g_qkv[(size_t)NT * D3];     // fp32 QKV
static __device__ __nv_bfloat16  g_xh[(size_t)NT * DD];      // hidden hi/lo
static __device__ __nv_bfloat16  g_xl[(size_t)NT * DD];
static __device__ __nv_bfloat16  g_ah[(size_t)NT * DD];      // attn out hi/lo
static __device__ __nv_bfloat16  g_al[(size_t)NT * DD];
static __device__ __nv_bfloat16  g_wqh[(size_t)D3 * DD];     // c_attn_w^T hi/lo [N][K]
static __device__ __nv_bfloat16  g_wql[(size_t)D3 * DD];
static __device__ __nv_bfloat16  g_wph[(size_t)DD * DD];     // c_proj_w^T hi/lo
static __device__ __nv_bfloat16  g_wpl[(size_t)DD * DD];

// ---------------------------------------------------------------------------
__device__ __forceinline__ uint32_t smem_u32(const void* p) {
    uint32_t a;
    asm("{ .reg .u64 t; cvta.to.shared.u64 t, %1; cvt.u32.u64 %0, t; }" : "=r"(a) : "l"(p));
    return a;
}

#define CP_ASYNC16(saddr, gptr) \
    asm volatile("cp.async.cg.shared.global [%0], [%1], 16;" :: "r"(saddr), "l"(gptr) : "memory")
#define CP_COMMIT()  asm volatile("cp.async.commit_group;" ::: "memory")
#define CP_WAIT0()   asm volatile("cp.async.wait_group 0;" ::: "memory")

#define LDMATRIX_X4(r0, r1, r2, r3, addr) \
    asm volatile("ldmatrix.sync.aligned.m8n8.x4.shared.b16 {%0,%1,%2,%3}, [%4];" \
        : "=r"(r0), "=r"(r1), "=r"(r2), "=r"(r3) : "r"(addr))

#define MMA_BF16(c, a, b) \
    asm volatile("mma.sync.aligned.m16n8k16.row.col.f32.bf16.bf16.f32 " \
        "{%0,%1,%2,%3}, {%4,%5,%6,%7}, {%8,%9}, {%0,%1,%2,%3};" \
        : "+f"((c)[0]), "+f"((c)[1]), "+f"((c)[2]), "+f"((c)[3]) \
        : "r"((a)[0]), "r"((a)[1]), "r"((a)[2]), "r"((a)[3]), "r"((b)[0]), "r"((b)[1]))

// ---------------------------------------------------------------------------
// Conversion kernels
// ---------------------------------------------------------------------------
__global__ void act_split(const float4* __restrict__ x,
                          uint2* __restrict__ hi, uint2* __restrict__ lo, int n4) {
    int i = blockIdx.x * blockDim.x + threadIdx.x;
    if (i >= n4) return;
    float4 v = x[i];
    float vv[4] = {v.x, v.y, v.z, v.w};
    union { uint2 u; __nv_bfloat16 b[4]; } H, L;
#pragma unroll
    for (int j = 0; j < 4; j++) {
        __nv_bfloat16 h = __float2bfloat16(vv[j]);
        H.b[j] = h;
        L.b[j] = __float2bfloat16(vv[j] - __bfloat162float(h));
    }
    hi[i] = H.u; lo[i] = L.u;
}

// W: [K,N] fp32 row-major -> Wt hi/lo: [N,K] bf16 row-major
__global__ void wt_split_t(const float* __restrict__ W,
                           __nv_bfloat16* __restrict__ hi, __nv_bfloat16* __restrict__ lo,
                           int K, int N) {
    __shared__ float t[32][33];
    const int kb = blockIdx.y * 32, nb = blockIdx.x * 32;
    const int tx = threadIdx.x, ty = threadIdx.y;
#pragma unroll
    for (int i = 0; i < 32; i += 8)
        t[ty + i][tx] = W[(size_t)(kb + ty + i) * N + nb + tx];
    __syncthreads();
#pragma unroll
    for (int i = 0; i < 32; i += 8) {
        float v = t[tx][ty + i];
        __nv_bfloat16 h = __float2bfloat16(v);
        size_t o = (size_t)(nb + ty + i) * K + kb + tx;
        hi[o] = h;
        lo[o] = __float2bfloat16(v - __bfloat162float(h));
    }
}

// ---------------------------------------------------------------------------
// HMMA GEMM: C[M,N] = (Ahi+Alo)[M,K] @ (Bhi+Blo)[N,K]^T + bias
// 128x128 CTA tile, 256 threads (2x4 warps, 64x32 per warp), BK=32,
// cp.async double buffering, 3-term bf16 split, fp32 accum.
// SMEM rows padded to 80B -> conflict-free ldmatrix.
// ---------------------------------------------------------------------------
#define BKC 32
#define ROWB 80                       // bytes per smem row (64B data + 16B pad)
#define TILEB (128 * ROWB)            // 10240 per operand tile
#define STAGEB (4 * TILEB)            // Ahi|Alo|Bhi|Blo = 40960
#define GSMEM (2 * STAGEB)            // 81920

extern __shared__ char g_dsmem[];

__global__ void __launch_bounds__(256, 1) gemm_mma(
    const __nv_bfloat16* __restrict__ Ahi, const __nv_bfloat16* __restrict__ Alo,
    const __nv_bfloat16* __restrict__ Bhi, const __nv_bfloat16* __restrict__ Blo,
    const float* __restrict__ bias, float* __restrict__ C,
    int M, int N, int K)
{
    const int tid  = threadIdx.x;
    const int wid  = tid >> 5;
    const int lane = tid & 31;
    const int wm   = wid >> 2;        // 0..1
    const int wn   = wid & 3;         // 0..3
    const int bm = blockIdx.y, bn = blockIdx.x;

    const __nv_bfloat16* srcs[4] = {
        Ahi + (size_t)(bm * 128) * K,
        Alo + (size_t)(bm * 128) * K,
        Bhi + (size_t)(bn * 128) * K,
        Blo + (size_t)(bn * 128) * K
    };

    const uint32_t sb = smem_u32(g_dsmem);

    float acc[4][4][4];
#pragma unroll
    for (int i = 0; i < 4; i++)
#pragma unroll
        for (int j = 0; j < 4; j++)
#pragma unroll
            for (int v = 0; v < 4; v++) acc[i][j][v] = 0.0f;

    const int NS = K / BKC;           // 32

    // ---- stage loader via cp.async ----
    auto load_stage = [&](int s, int buf) {
        const int k0 = s * BKC;
        const uint32_t base = sb + buf * STAGEB;
#pragma unroll
        for (int i = 0; i < 8; i++) {
            const int tile = i >> 1;
            const int idx  = ((i & 1) << 8) + tid;   // 0..511
            const int r    = idx >> 2;
            const int c    = idx & 3;
            const uint32_t sa = base + tile * TILEB + r * ROWB + c * 16;
            const __nv_bfloat16* g = srcs[tile] + (size_t)r * K + k0 + c * 8;
            CP_ASYNC16(sa, g);
        }
        CP_COMMIT();
    };

    load_stage(0, 0);
    CP_WAIT0();
    __syncthreads();

    // ldmatrix lane addressing (constant per thread)
    const int a_row  = (lane & 15);
    const int a_koff = (lane >> 4) * 16;
    const int b_blk  = lane >> 3;
    const int b_row8 = lane & 7;
    const int b_noff = ((b_blk >> 1) << 3) + b_row8;
    const int b_koff = (b_blk & 1) * 16;

    for (int s = 0; s < NS; s++) {
        const int buf = s & 1;
        if (s + 1 < NS) load_stage(s + 1, buf ^ 1);

        const uint32_t st = sb + buf * STAGEB;
#pragma unroll
        for (int ks = 0; ks < 2; ks++) {
            const int kb = ks * 32;   // byte offset of k16 sub-block

            uint32_t ah[4][4], al[4][4], bh[4][2], bl[4][2];
#pragma unroll
            for (int mt = 0; mt < 4; mt++) {
                const uint32_t ar = st + (wm * 64 + mt * 16 + a_row) * ROWB + kb + a_koff;
                LDMATRIX_X4(ah[mt][0], ah[mt][1], ah[mt][2], ah[mt][3], ar);
                LDMATRIX_X4(al[mt][0], al[mt][1], al[mt][2], al[mt][3], ar + TILEB);
            }
#pragma unroll
            for (int p = 0; p < 2; p++) {
                const uint32_t br = st + 2 * TILEB +
                    (wn * 32 + p * 16 + b_noff) * ROWB + kb + b_koff;
                LDMATRIX_X4(bh[2 * p][0], bh[2 * p][1], bh[2 * p + 1][0], bh[2 * p + 1][1], br);
                LDMATRIX_X4(bl[2 * p][0], bl[2 * p][1], bl[2 * p + 1][0], bl[2 * p + 1][1], br + TILEB);
            }

#pragma unroll
            for (int mt = 0; mt < 4; mt++)
#pragma unroll
                for (int nt = 0; nt < 4; nt++) {
                    MMA_BF16(acc[mt][nt], ah[mt], bh[nt]);
                    MMA_BF16(acc[mt][nt], al[mt], bh[nt]);
                    MMA_BF16(acc[mt][nt], ah[mt], bl[nt]);
                }
        }

        if (s + 1 < NS) {
            CP_WAIT0();
            __syncthreads();
        }
    }

    // ---- epilogue ----
    const int r0 = bm * 128 + wm * 64 + (lane >> 2);
    const int c0 = bn * 128 + wn * 32 + (lane & 3) * 2;
#pragma unroll
    for (int mt = 0; mt < 4; mt++) {
#pragma unroll
        for (int nt = 0; nt < 4; nt++) {
            const int row = r0 + mt * 16;
            const int col = c0 + nt * 8;
            float2 o0, o1;
            o0.x = acc[mt][nt][0] + bias[col];
            o0.y = acc[mt][nt][1] + bias[col + 1];
            o1.x = acc[mt][nt][2] + bias[col];
            o1.y = acc[mt][nt][3] + bias[col + 1];
            *(float2*)(C + (size_t)row * N + col) = o0;
            *(float2*)(C + (size_t)(row + 8) * N + col) = o1;
        }
    }
}

// ---------------------------------------------------------------------------
// Flash attention (causal), fp32 math. Writes bf16 hi/lo splits directly.
// ---------------------------------------------------------------------------
__global__ __launch_bounds__(128) void flash_attn(
    const float* __restrict__ qkv,
    __nv_bfloat16* __restrict__ attn_hi, __nv_bfloat16* __restrict__ attn_lo)
{
    __shared__ float4 ks4[32][16];
    __shared__ float4 vs4[32][16];

    const int tid   = threadIdx.x;
    const int qtile = blockIdx.x;
    const int bh    = blockIdx.y;
    const int b     = bh >> 4;
    const int h     = bh & 15;

    const int bS = b * SS;
    const int qi = qtile * 128 + tid;

    float4 q4[16];
    {
        const float* qp = qkv + (size_t)(bS + qi) * D3 + h * HD;
#pragma unroll
        for (int c = 0; c < 16; c++) {
            float4 v = *(const float4*)(qp + c * 4);
            v.x *= 0.125f; v.y *= 0.125f; v.z *= 0.125f; v.w *= 0.125f;
            q4[c] = v;
        }
    }

    float4 acc4[16];
#pragma unroll
    for (int c = 0; c < 16; c++) acc4[c] = make_float4(0.f, 0.f, 0.f, 0.f);
    float m = -1e30f, l = 0.0f;

    const int n_tiles = (qtile + 1) * 4;
    for (int kt = 0; kt < n_tiles; kt++) {
        const int k0 = kt * 32;
        __syncthreads();
#pragma unroll
        for (int r = 0; r < 4; r++) {
            const int i = tid + 128 * r;
            const int row = i >> 4, col = i & 15;
            const size_t base = (size_t)(bS + k0 + row) * D3 + h * HD + col * 4;
            ks4[row][col] = *(const float4*)(qkv + base + DD);
            vs4[row][col] = *(const float4*)(qkv + base + 2 * DD);
        }
        __syncthreads();

        float s[32];
#pragma unroll
        for (int j = 0; j < 32; j++) {
            float sum = 0.0f;
#pragma unroll
            for (int c = 0; c < 16; c++) {
                float4 kk = ks4[j][c];
                sum += q4[c].x * kk.x + q4[c].y * kk.y + q4[c].z * kk.z + q4[c].w * kk.w;
            }
            s[j] = sum;
        }

        if (k0 + 31 > qi) {
#pragma unroll
            for (int j = 0; j < 32; j++)
                if (k0 + j > qi) s[j] = -1e30f;
        }

        float m_new = m;
#pragma unroll
        for (int j = 0; j < 32; j++) m_new = fmaxf(m_new, s[j]);

        const float alpha = __expf(m - m_new);
        l *= alpha;
#pragma unroll
        for (int c = 0; c < 16; c++) {
            acc4[c].x *= alpha; acc4[c].y *= alpha;
            acc4[c].z *= alpha; acc4[c].w *= alpha;
        }

#pragma unroll
        for (int j = 0; j < 32; j++) {
            const float p = __expf(s[j] - m_new);
            l += p;
            s[j] = p;
        }

#pragma unroll
        for (int j = 0; j < 32; j++) {
            const float p = s[j];
#pragma unroll
            for (int c = 0; c < 16; c++) {
                float4 vv = vs4[j][c];
                acc4[c].x += p * vv.x; acc4[c].y += p * vv.y;
                acc4[c].z += p * vv.z; acc4[c].w += p * vv.w;
            }
        }
        m = m_new;
    }

    const float inv_l = 1.0f / l;
    __nv_bfloat16* oh = attn_hi + (size_t)(bS + qi) * DD + h * HD;
    __nv_bfloat16* ol = attn_lo + (size_t)(bS + qi) * DD + h * HD;
#pragma unroll
    for (int c = 0; c < 16; c++) {
        float ov[4] = {acc4[c].x * inv_l, acc4[c].y * inv_l,
                       acc4[c].z * inv_l, acc4[c].w * inv_l};
        union { uint2 u; __nv_bfloat16 b[4]; } H, L;
#pragma unroll
        for (int j = 0; j < 4; j++) {
            __nv_bfloat16 hh = __float2bfloat16(ov[j]);
            H.b[j] = hh;
            L.b[j] = __float2bfloat16(ov[j] - __bfloat162float(hh));
        }
        ((uint2*)oh)[c] = H.u;
        ((uint2*)ol)[c] = L.u;
    }
}

// ---------------------------------------------------------------------------
extern "C" void kernel_launch(void* const* d_in, const int* in_sizes, int n_in,
                              void* d_out, int out_size)
{
    const float* hidden   = (const float*)d_in[0];
    const float* c_attn_w = (const float*)d_in[1];
    const float* c_attn_b = (const float*)d_in[2];
    const float* c_proj_w = (const float*)d_in[3];
    const float* c_proj_b = (const float*)d_in[4];
    float* out = (float*)d_out;

    float *qkv;
    __nv_bfloat16 *xh, *xl, *ah, *al, *wqh, *wql, *wph, *wpl;
    cudaGetSymbolAddress((void**)&qkv, g_qkv);
    cudaGetSymbolAddress((void**)&xh,  g_xh);
    cudaGetSymbolAddress((void**)&xl,  g_xl);
    cudaGetSymbolAddress((void**)&ah,  g_ah);
    cudaGetSymbolAddress((void**)&al,  g_al);
    cudaGetSymbolAddress((void**)&wqh, g_wqh);
    cudaGetSymbolAddress((void**)&wql, g_wql);
    cudaGetSymbolAddress((void**)&wph, g_wph);
    cudaGetSymbolAddress((void**)&wpl, g_wpl);

    cudaFuncSetAttribute(gemm_mma, cudaFuncAttributeMaxDynamicSharedMemorySize, GSMEM);

    // weight transpose+split
    wt_split_t<<<dim3(D3 / 32, DD / 32), dim3(32, 8)>>>(c_attn_w, wqh, wql, DD, D3);
    wt_split_t<<<dim3(DD / 32, DD / 32), dim3(32, 8)>>>(c_proj_w, wph, wpl, DD, DD);

    // hidden -> bf16 hi/lo
    {
        const int n4 = NT * DD / 4;
        act_split<<<(n4 + 255) / 256, 256>>>((const float4*)hidden, (uint2*)xh, (uint2*)xl, n4);
    }

    // 1) QKV projection (HMMA tensor cores)
    gemm_mma<<<dim3(D3 / 128, NT / 128), 256, GSMEM>>>(xh, xl, wqh, wql, c_attn_b, qkv, NT, D3, DD);

    // 2) causal flash attention (fp32), emits bf16 hi/lo
    flash_attn<<<dim3(SS / 128, BB * HH), 128>>>(qkv, ah, al);

    // 3) output projection (HMMA tensor cores)
    gemm_mma<<<dim3(DD / 128, NT / 128), 256, GSMEM>>>(ah, al, wph, wpl, c_proj_b, out, NT, DD, DD);
}

// round 4
// speedup vs baseline: 3.2640x; 2.6354x over previous
#include <cuda_runtime.h>
#include <cuda_bf16.h>
#include <cstdint>

// Problem constants
#define BB 4
#define SS 2048
#define DD 1024
#define HH 16
#define HD 64
#define NT (BB * SS)        // 8192 tokens
#define D3 (3 * DD)         // 3072

// ---------------------------------------------------------------------------
// Scratch (device globals — no runtime allocation)
// ---------------------------------------------------------------------------
static __device__ __nv_bfloat16  g_qkvh[(size_t)NT * D3];   // qkv hi/lo (bf16)
static __device__ __nv_bfloat16  g_qkvl[(size_t)NT * D3];
static __device__ __nv_bfloat16  g_xh[(size_t)NT * DD];     // hidden hi/lo
static __device__ __nv_bfloat16  g_xl[(size_t)NT * DD];
static __device__ __nv_bfloat16  g_ah[(size_t)NT * DD];     // attn out hi/lo
static __device__ __nv_bfloat16  g_al[(size_t)NT * DD];
static __device__ __nv_bfloat16  g_wqh[(size_t)D3 * DD];    // c_attn_w^T hi/lo [N][K]
static __device__ __nv_bfloat16  g_wql[(size_t)D3 * DD];
static __device__ __nv_bfloat16  g_wph[(size_t)DD * DD];    // c_proj_w^T hi/lo
static __device__ __nv_bfloat16  g_wpl[(size_t)DD * DD];

// ---------------------------------------------------------------------------
__device__ __forceinline__ uint32_t smem_u32(const void* p) {
    uint32_t a;
    asm("{ .reg .u64 t; cvta.to.shared.u64 t, %1; cvt.u32.u64 %0, t; }" : "=r"(a) : "l"(p));
    return a;
}

#define CP_ASYNC16(saddr, gptr) \
    asm volatile("cp.async.cg.shared.global [%0], [%1], 16;" :: "r"(saddr), "l"(gptr) : "memory")
#define CP_COMMIT()  asm volatile("cp.async.commit_group;" ::: "memory")
#define CP_WAIT0()   asm volatile("cp.async.wait_group 0;" ::: "memory")
#define CP_WAIT1()   asm volatile("cp.async.wait_group 1;" ::: "memory")

#define LDMATRIX_X4(r0, r1, r2, r3, addr) \
    asm volatile("ldmatrix.sync.aligned.m8n8.x4.shared.b16 {%0,%1,%2,%3}, [%4];" \
        : "=r"(r0), "=r"(r1), "=r"(r2), "=r"(r3) : "r"(addr))

#define LDMATRIX_X4_T(r0, r1, r2, r3, addr) \
    asm volatile("ldmatrix.sync.aligned.m8n8.x4.trans.shared.b16 {%0,%1,%2,%3}, [%4];" \
        : "=r"(r0), "=r"(r1), "=r"(r2), "=r"(r3) : "r"(addr))

#define MMA_BF16(c, a, b) \
    asm volatile("mma.sync.aligned.m16n8k16.row.col.f32.bf16.bf16.f32 " \
        "{%0,%1,%2,%3}, {%4,%5,%6,%7}, {%8,%9}, {%0,%1,%2,%3};" \
        : "+f"((c)[0]), "+f"((c)[1]), "+f"((c)[2]), "+f"((c)[3]) \
        : "r"((a)[0]), "r"((a)[1]), "r"((a)[2]), "r"((a)[3]), "r"((b)[0]), "r"((b)[1]))

__device__ __forceinline__ uint32_t pack_bf16(float a, float b) {
    __nv_bfloat162 t = __floats2bfloat162_rn(a, b);
    return *reinterpret_cast<uint32_t*>(&t);
}

// ---------------------------------------------------------------------------
// Conversion kernels
// ---------------------------------------------------------------------------
__global__ void act_split(const float4* __restrict__ x,
                          uint2* __restrict__ hi, uint2* __restrict__ lo, int n4) {
    int i = blockIdx.x * blockDim.x + threadIdx.x;
    if (i >= n4) return;
    float4 v = x[i];
    float vv[4] = {v.x, v.y, v.z, v.w};
    union { uint2 u; __nv_bfloat16 b[4]; } H, L;
#pragma unroll
    for (int j = 0; j < 4; j++) {
        __nv_bfloat16 h = __float2bfloat16(vv[j]);
        H.b[j] = h;
        L.b[j] = __float2bfloat16(vv[j] - __bfloat162float(h));
    }
    hi[i] = H.u; lo[i] = L.u;
}

__global__ void wt_split_t(const float* __restrict__ W,
                           __nv_bfloat16* __restrict__ hi, __nv_bfloat16* __restrict__ lo,
                           int K, int N) {
    __shared__ float t[32][33];
    const int kb = blockIdx.y * 32, nb = blockIdx.x * 32;
    const int tx = threadIdx.x, ty = threadIdx.y;
#pragma unroll
    for (int i = 0; i < 32; i += 8)
        t[ty + i][tx] = W[(size_t)(kb + ty + i) * N + nb + tx];
    __syncthreads();
#pragma unroll
    for (int i = 0; i < 32; i += 8) {
        float v = t[tx][ty + i];
        __nv_bfloat16 h = __float2bfloat16(v);
        size_t o = (size_t)(nb + ty + i) * K + kb + tx;
        hi[o] = h;
        lo[o] = __float2bfloat16(v - __bfloat162float(h));
    }
}

// ---------------------------------------------------------------------------
// HMMA GEMM: C = (Ahi+Alo)[M,K] @ (Bhi+Blo)[N,K]^T + bias
// Output either fp32 (Cf) or bf16 hi/lo pair (Ch/Cl).
// ---------------------------------------------------------------------------
#define BKC 32
#define ROWB 80
#define TILEB (128 * ROWB)
#define STAGEB (4 * TILEB)
#define GSMEM (2 * STAGEB)

extern __shared__ char g_dsmem[];

__global__ void __launch_bounds__(256, 1) gemm_mma(
    const __nv_bfloat16* __restrict__ Ahi, const __nv_bfloat16* __restrict__ Alo,
    const __nv_bfloat16* __restrict__ Bhi, const __nv_bfloat16* __restrict__ Blo,
    const float* __restrict__ bias, float* __restrict__ Cf,
    __nv_bfloat16* __restrict__ Ch, __nv_bfloat16* __restrict__ Cl,
    int M, int N, int K)
{
    const int tid  = threadIdx.x;
    const int wid  = tid >> 5;
    const int lane = tid & 31;
    const int wm   = wid >> 2;
    const int wn   = wid & 3;
    const int bm = blockIdx.y, bn = blockIdx.x;

    const __nv_bfloat16* srcs[4] = {
        Ahi + (size_t)(bm * 128) * K,
        Alo + (size_t)(bm * 128) * K,
        Bhi + (size_t)(bn * 128) * K,
        Blo + (size_t)(bn * 128) * K
    };

    const uint32_t sb = smem_u32(g_dsmem);

    float acc[4][4][4];
#pragma unroll
    for (int i = 0; i < 4; i++)
#pragma unroll
        for (int j = 0; j < 4; j++)
#pragma unroll
            for (int v = 0; v < 4; v++) acc[i][j][v] = 0.0f;

    const int NS = K / BKC;

    auto load_stage = [&](int s, int buf) {
        const int k0 = s * BKC;
        const uint32_t base = sb + buf * STAGEB;
#pragma unroll
        for (int i = 0; i < 8; i++) {
            const int tile = i >> 1;
            const int idx  = ((i & 1) << 8) + tid;
            const int r    = idx >> 2;
            const int c    = idx & 3;
            const uint32_t sa = base + tile * TILEB + r * ROWB + c * 16;
            const __nv_bfloat16* g = srcs[tile] + (size_t)r * K + k0 + c * 8;
            CP_ASYNC16(sa, g);
        }
        CP_COMMIT();
    };

    load_stage(0, 0);
    CP_WAIT0();
    __syncthreads();

    const int a_row  = (lane & 15);
    const int a_koff = (lane >> 4) * 16;
    const int b_blk  = lane >> 3;
    const int b_row8 = lane & 7;
    const int b_noff = ((b_blk >> 1) << 3) + b_row8;
    const int b_koff = (b_blk & 1) * 16;

    for (int s = 0; s < NS; s++) {
        const int buf = s & 1;
        if (s + 1 < NS) load_stage(s + 1, buf ^ 1);

        const uint32_t st = sb + buf * STAGEB;
#pragma unroll
        for (int ks = 0; ks < 2; ks++) {
            const int kb = ks * 32;

            uint32_t ah[4][4], al[4][4], bh[4][2], bl[4][2];
#pragma unroll
            for (int mt = 0; mt < 4; mt++) {
                const uint32_t ar = st + (wm * 64 + mt * 16 + a_row) * ROWB + kb + a_koff;
                LDMATRIX_X4(ah[mt][0], ah[mt][1], ah[mt][2], ah[mt][3], ar);
                LDMATRIX_X4(al[mt][0], al[mt][1], al[mt][2], al[mt][3], ar + TILEB);
            }
#pragma unroll
            for (int p = 0; p < 2; p++) {
                const uint32_t br = st + 2 * TILEB +
                    (wn * 32 + p * 16 + b_noff) * ROWB + kb + b_koff;
                LDMATRIX_X4(bh[2 * p][0], bh[2 * p][1], bh[2 * p + 1][0], bh[2 * p + 1][1], br);
                LDMATRIX_X4(bl[2 * p][0], bl[2 * p][1], bl[2 * p + 1][0], bl[2 * p + 1][1], br + TILEB);
            }

#pragma unroll
            for (int mt = 0; mt < 4; mt++)
#pragma unroll
                for (int nt = 0; nt < 4; nt++) {
                    MMA_BF16(acc[mt][nt], ah[mt], bh[nt]);
                    MMA_BF16(acc[mt][nt], al[mt], bh[nt]);
                    MMA_BF16(acc[mt][nt], ah[mt], bl[nt]);
                }
        }

        if (s + 1 < NS) {
            CP_WAIT0();
            __syncthreads();
        }
    }

    const int r0 = bm * 128 + wm * 64 + (lane >> 2);
    const int c0 = bn * 128 + wn * 32 + (lane & 3) * 2;
    if (Cf) {
#pragma unroll
        for (int mt = 0; mt < 4; mt++)
#pragma unroll
            for (int nt = 0; nt < 4; nt++) {
                const int row = r0 + mt * 16;
                const int col = c0 + nt * 8;
                float2 o0, o1;
                o0.x = acc[mt][nt][0] + bias[col];
                o0.y = acc[mt][nt][1] + bias[col + 1];
                o1.x = acc[mt][nt][2] + bias[col];
                o1.y = acc[mt][nt][3] + bias[col + 1];
                *(float2*)(Cf + (size_t)row * N + col) = o0;
                *(float2*)(Cf + (size_t)(row + 8) * N + col) = o1;
            }
    } else {
#pragma unroll
        for (int mt = 0; mt < 4; mt++)
#pragma unroll
            for (int nt = 0; nt < 4; nt++) {
                const int row = r0 + mt * 16;
                const int col = c0 + nt * 8;
                const float b0 = bias[col], b1 = bias[col + 1];
#pragma unroll
                for (int hf = 0; hf < 2; hf++) {
                    const float v0 = acc[mt][nt][2 * hf]     + b0;
                    const float v1 = acc[mt][nt][2 * hf + 1] + b1;
                    const float h0 = __bfloat162float(__float2bfloat16(v0));
                    const float h1 = __bfloat162float(__float2bfloat16(v1));
                    const size_t off = (size_t)(row + 8 * hf) * N + col;
                    *(uint32_t*)(Ch + off) = pack_bf16(h0, h1);
                    *(uint32_t*)(Cl + off) = pack_bf16(v0 - h0, v1 - h1);
                }
            }
    }
}

// ---------------------------------------------------------------------------
// Tensor-core causal flash attention.
// CTA: 128 q rows of one (b,h); 8 warps x 16 rows. 64-key K/V tiles (hi/lo),
// cp.async double buffered. 3-term bf16 split on both QK^T and PV.
// ---------------------------------------------------------------------------
#define AROWB 144                    // 128B row + 16B pad (conflict-free ldmatrix)
#define ATILE (64 * AROWB)           // 9216
#define ASTAGE (4 * ATILE)           // Kh|Kl|Vh|Vl = 36864
#define ASMEM (2 * ASTAGE)           // 73728

__global__ void __launch_bounds__(256) attn_mma(
    const __nv_bfloat16* __restrict__ QKVh, const __nv_bfloat16* __restrict__ QKVl,
    __nv_bfloat16* __restrict__ Oh, __nv_bfloat16* __restrict__ Ol)
{
    const int tid  = threadIdx.x;
    const int wid  = tid >> 5;
    const int lane = tid & 31;
    const int qtile = (gridDim.x - 1) - blockIdx.x;   // heavy tiles first
    const int bh = blockIdx.y;
    const int b  = bh >> 4;
    const int h  = bh & 15;
    const int bS = b * SS;
    const int qbase = qtile * 128 + wid * 16;

    const uint32_t sb = smem_u32(g_dsmem);

    // ---- stage Q (128 rows x 64 dims, hi+lo) into smem ----
#pragma unroll
    for (int i = 0; i < 4; i++) {
        const int idx = i * 256 + tid;          // 0..1023
        const int r = idx >> 3, c = idx & 7;
        const size_t g = (size_t)(bS + qtile * 128 + r) * D3 + h * HD + c * 8;
        CP_ASYNC16(sb + r * AROWB + c * 16, QKVh + g);
        CP_ASYNC16(sb + 128 * AROWB + r * AROWB + c * 16, QKVl + g);
    }
    CP_COMMIT();
    CP_WAIT0();
    __syncthreads();

    // ---- build Q fragments ----
    uint32_t qh[4][4], ql[4][4];
    const int a_row  = lane & 15;
    const int a_koff = (lane >> 4) * 16;
    {
        const uint32_t qr = sb + (wid * 16 + a_row) * AROWB + a_koff;
#pragma unroll
        for (int ks = 0; ks < 4; ks++) {
            LDMATRIX_X4(qh[ks][0], qh[ks][1], qh[ks][2], qh[ks][3], qr + ks * 32);
            LDMATRIX_X4(ql[ks][0], ql[ks][1], ql[ks][2], ql[ks][3],
                        qr + 128 * AROWB + ks * 32);
        }
    }
    __syncthreads();   // Q staging region about to be reused for K/V

    // ---- K/V stage loader ----
    auto load_kv = [&](int kt, int buf) {
        const int k0 = kt * 64;
        const uint32_t base = sb + buf * ASTAGE;
#pragma unroll
        for (int i = 0; i < 8; i++) {
            const int idx  = i * 256 + tid;     // 0..2047
            const int tile = idx >> 9;          // Kh,Kl,Vh,Vl
            const int r    = (idx >> 3) & 63;
            const int c    = idx & 7;
            const size_t g = (size_t)(bS + k0 + r) * D3 +
                             ((tile < 2) ? DD : 2 * DD) + h * HD + c * 8;
            const __nv_bfloat16* src = (tile & 1) ? QKVl : QKVh;
            CP_ASYNC16(base + tile * ATILE + r * AROWB + c * 16, src + g);
        }
        CP_COMMIT();
    };

    float o[8][4];
#pragma unroll
    for (int n = 0; n < 8; n++)
#pragma unroll
        for (int j = 0; j < 4; j++) o[n][j] = 0.0f;
    float mrow[2] = {-1e30f, -1e30f};
    float lrow[2] = {0.0f, 0.0f};

    // K (B-frag, non-trans) lane addressing
    const int b_blk  = lane >> 3;
    const int b_row8 = lane & 7;
    const int b_noff = ((b_blk >> 1) << 3) + b_row8;
    const int b_koff = (b_blk & 1) * 16;
    // V (B-frag via ldmatrix.trans) lane addressing
    const int v_row  = lane & 15;
    const int v_coff = ((lane >> 4) & 1) * 16;

    const int ntl = 2 * qtile + 2;
    load_kv(0, 0);

    for (int kt = 0; kt < ntl; kt++) {
        const int buf = kt & 1;
        const int k0 = kt * 64;
        if (kt + 1 < ntl) { load_kv(kt + 1, buf ^ 1); CP_WAIT1(); }
        else              { CP_WAIT0(); }
        __syncthreads();

        if (k0 <= qbase + 15) {     // warp has unmasked work in this tile
            const uint32_t kbse = sb + buf * ASTAGE;
            const uint32_t vbse = kbse + 2 * ATILE;

            // ---- S = Q K^T (3-term split) ----
            float s[8][4];
#pragma unroll
            for (int n = 0; n < 8; n++)
#pragma unroll
                for (int j = 0; j < 4; j++) s[n][j] = 0.0f;

#pragma unroll
            for (int p = 0; p < 4; p++) {
#pragma unroll
                for (int ks = 0; ks < 4; ks++) {
                    uint32_t kh[4], kl[4];
                    const uint32_t ar = kbse + (p * 16 + b_noff) * AROWB + ks * 32 + b_koff;
                    LDMATRIX_X4(kh[0], kh[1], kh[2], kh[3], ar);
                    LDMATRIX_X4(kl[0], kl[1], kl[2], kl[3], ar + ATILE);
                    uint32_t bh0[2] = {kh[0], kh[1]}, bh1[2] = {kh[2], kh[3]};
                    uint32_t bl0[2] = {kl[0], kl[1]}, bl1[2] = {kl[2], kl[3]};
                    MMA_BF16(s[2 * p],     qh[ks], bh0);
                    MMA_BF16(s[2 * p],     ql[ks], bh0);
                    MMA_BF16(s[2 * p],     qh[ks], bl0);
                    MMA_BF16(s[2 * p + 1], qh[ks], bh1);
                    MMA_BF16(s[2 * p + 1], ql[ks], bh1);
                    MMA_BF16(s[2 * p + 1], qh[ks], bl1);
                }
            }

            // ---- masking + online softmax ----
            const bool need_mask = (k0 + 63 > qbase);
            const int row0 = qbase + (lane >> 2);
            const int colb = k0 + (lane & 3) * 2;
#pragma unroll
            for (int hf = 0; hf < 2; hf++) {
                const int row = row0 + 8 * hf;
                float mx = mrow[hf];
#pragma unroll
                for (int n = 0; n < 8; n++) {
                    float v0 = s[n][2 * hf]     * 0.125f;
                    float v1 = s[n][2 * hf + 1] * 0.125f;
                    if (need_mask) {
                        const int col = colb + 8 * n;
                        if (col > row)     v0 = -1e30f;
                        if (col + 1 > row) v1 = -1e30f;
                    }
                    s[n][2 * hf] = v0; s[n][2 * hf + 1] = v1;
                    mx = fmaxf(mx, fmaxf(v0, v1));
                }
                mx = fmaxf(mx, __shfl_xor_sync(0xffffffffu, mx, 1));
                mx = fmaxf(mx, __shfl_xor_sync(0xffffffffu, mx, 2));
                const float alpha = __expf(mrow[hf] - mx);
                lrow[hf] *= alpha;
#pragma unroll
                for (int n = 0; n < 8; n++) {
                    o[n][2 * hf]     *= alpha;
                    o[n][2 * hf + 1] *= alpha;
                }
                float ls = 0.0f;
#pragma unroll
                for (int n = 0; n < 8; n++) {
                    const float p0 = __expf(s[n][2 * hf]     - mx);
                    const float p1 = __expf(s[n][2 * hf + 1] - mx);
                    s[n][2 * hf] = p0; s[n][2 * hf + 1] = p1;
                    ls += p0 + p1;
                }
                lrow[hf] += ls;
                mrow[hf] = mx;
            }

            // ---- O += P V (3-term split) ----
#pragma unroll
            for (int ks = 0; ks < 4; ks++) {
                uint32_t ph[4], pl[4];
#pragma unroll
                for (int q2 = 0; q2 < 2; q2++) {
                    const float* pv = s[2 * ks + q2];
#pragma unroll
                    for (int e = 0; e < 2; e++) {
                        const float v0 = pv[2 * e], v1 = pv[2 * e + 1];
                        const float h0 = __bfloat162float(__float2bfloat16(v0));
                        const float h1 = __bfloat162float(__float2bfloat16(v1));
                        ph[q2 * 2 + e] = pack_bf16(h0, h1);
                        pl[q2 * 2 + e] = pack_bf16(v0 - h0, v1 - h1);
                    }
                }
#pragma unroll
                for (int np = 0; np < 4; np++) {
                    uint32_t vh[4], vl[4];
                    const uint32_t va = vbse + (ks * 16 + v_row) * AROWB + np * 32 + v_coff;
                    LDMATRIX_X4_T(vh[0], vh[1], vh[2], vh[3], va);
                    LDMATRIX_X4_T(vl[0], vl[1], vl[2], vl[3], va + ATILE);
                    uint32_t vh0[2] = {vh[0], vh[1]}, vh1[2] = {vh[2], vh[3]};
                    uint32_t vl0[2] = {vl[0], vl[1]}, vl1[2] = {vl[2], vl[3]};
                    MMA_BF16(o[2 * np],     ph, vh0);
                    MMA_BF16(o[2 * np],     pl, vh0);
                    MMA_BF16(o[2 * np],     ph, vl0);
                    MMA_BF16(o[2 * np + 1], ph, vh1);
                    MMA_BF16(o[2 * np + 1], pl, vh1);
                    MMA_BF16(o[2 * np + 1], ph, vl1);
                }
            }
        }
        __syncthreads();   // all warps done reading buf before it is refilled
    }

    // ---- finalize: divide by l, write bf16 hi/lo ----
    float inv[2];
#pragma unroll
    for (int hf = 0; hf < 2; hf++) {
        float l = lrow[hf];
        l += __shfl_xor_sync(0xffffffffu, l, 1);
        l += __shfl_xor_sync(0xffffffffu, l, 2);
        inv[hf] = 1.0f / l;
    }
    const int row0 = qbase + (lane >> 2);
    const int colb = h * HD + (lane & 3) * 2;
#pragma unroll
    for (int hf = 0; hf < 2; hf++) {
        const size_t rof = (size_t)(bS + row0 + 8 * hf) * DD;
#pragma unroll
        for (int n = 0; n < 8; n++) {
            const float v0 = o[n][2 * hf]     * inv[hf];
            const float v1 = o[n][2 * hf + 1] * inv[hf];
            const float h0 = __bfloat162float(__float2bfloat16(v0));
            const float h1 = __bfloat162float(__float2bfloat16(v1));
            const size_t off = rof + colb + n * 8;
            *(uint32_t*)(Oh + off) = pack_bf16(h0, h1);
            *(uint32_t*)(Ol + off) = pack_bf16(v0 - h0, v1 - h1);
        }
    }
}

// ---------------------------------------------------------------------------
extern "C" void kernel_launch(void* const* d_in, const int* in_sizes, int n_in,
                              void* d_out, int out_size)
{
    const float* hidden   = (const float*)d_in[0];
    const float* c_attn_w = (const float*)d_in[1];
    const float* c_attn_b = (const float*)d_in[2];
    const float* c_proj_w = (const float*)d_in[3];
    const float* c_proj_b = (const float*)d_in[4];
    float* out = (float*)d_out;

    __nv_bfloat16 *qkvh, *qkvl, *xh, *xl, *ah, *al, *wqh, *wql, *wph, *wpl;
    cudaGetSymbolAddress((void**)&qkvh, g_qkvh);
    cudaGetSymbolAddress((void**)&qkvl, g_qkvl);
    cudaGetSymbolAddress((void**)&xh,  g_xh);
    cudaGetSymbolAddress((void**)&xl,  g_xl);
    cudaGetSymbolAddress((void**)&ah,  g_ah);
    cudaGetSymbolAddress((void**)&al,  g_al);
    cudaGetSymbolAddress((void**)&wqh, g_wqh);
    cudaGetSymbolAddress((void**)&wql, g_wql);
    cudaGetSymbolAddress((void**)&wph, g_wph);
    cudaGetSymbolAddress((void**)&wpl, g_wpl);

    cudaFuncSetAttribute(gemm_mma, cudaFuncAttributeMaxDynamicSharedMemorySize, GSMEM);
    cudaFuncSetAttribute(attn_mma, cudaFuncAttributeMaxDynamicSharedMemorySize, ASMEM);

    wt_split_t<<<dim3(D3 / 32, DD / 32), dim3(32, 8)>>>(c_attn_w, wqh, wql, DD, D3);
    wt_split_t<<<dim3(DD / 32, DD / 32), dim3(32, 8)>>>(c_proj_w, wph, wpl, DD, DD);

    {
        const int n4 = NT * DD / 4;
        act_split<<<(n4 + 255) / 256, 256>>>((const float4*)hidden, (uint2*)xh, (uint2*)xl, n4);
    }

    // 1) QKV projection -> bf16 hi/lo directly
    gemm_mma<<<dim3(D3 / 128, NT / 128), 256, GSMEM>>>(
        xh, xl, wqh, wql, c_attn_b, nullptr, qkvh, qkvl, NT, D3, DD);

    // 2) tensor-core causal flash attention
    attn_mma<<<dim3(SS / 128, BB * HH), 256, ASMEM>>>(qkvh, qkvl, ah, al);

    // 3) output projection -> fp32
    gemm_mma<<<dim3(DD / 128, NT / 128), 256, GSMEM>>>(
        ah, al, wph, wpl, c_proj_b, out, nullptr, nullptr, NT, DD, DD);
}